// round 2
// baseline (speedup 1.0000x reference)
#include <cuda_runtime.h>

// ---------------------------------------------------------------------------
// InterpolatingBSpline2d, round 2.
//
// Coef solve: boundary rows eliminated analytically; interior is a constant
// (1/6, 2/3, 1/6) tridiagonal solved by Thomas with COMPILE-TIME factors
// (round 1 lost ~19us to 62 serial runtime fp32 divides). Both passes fused
// into one kernel; intermediate in padded smem (65-stride, conflict-free).
//
// Interp: 4-lane cooperative gather. Lane dx = lane&3 loads the 4 float4
// chunks of x-row (ix+dx); per-instruction bank-quads are C + 2*dx + j,
// distinct within a point, so worst case is a 2-way conflict between the two
// points sharing an 8-lane phase (expected factor 1.5 vs ~2.4 for the
// per-thread random gather). Cross-lane reduction: 2 shfl_xor butterfly
// rounds over the 4 dx lanes.
// ---------------------------------------------------------------------------

#define M_GRID   64
#define NP2      66
#define NINNER   62
#define NCH      4
#define CX_PAD   65      // smem inner stride for stage-1 intermediate

__device__ float g_coefs[NP2 * NP2 * NCH];   // (x*66 + y)*4 + c

// ---- compile-time Thomas factors ------------------------------------------
struct Fac { float cp[NINNER]; float invden[NINNER]; };

constexpr Fac make_fac() {
    Fac f{};
    const float B = 2.0f / 3.0f, A = 1.0f / 6.0f;
    float c = A / B;
    f.cp[0] = c;
    f.invden[0] = 1.0f / B;
    for (int m = 1; m < NINNER; ++m) {
        float den = B - A * c;
        float inv = 1.0f / den;
        c = A * inv;
        f.cp[m] = c;
        f.invden[m] = inv;
    }
    return f;
}
__constant__ Fac FAC = make_fac();

// Solve 66-unknown natural-BC spline system for one 64-sample RHS.
__device__ __forceinline__ void spline_solve_1d(
    const float* __restrict__ src, int sstride,
    float* __restrict__ dst, int dstride)
{
    const float SIXTH = 1.0f / 6.0f;
    float d0 = src[0];
    float dp[NINNER];

    dp[0] = (src[sstride] - d0 * SIXTH) * FAC.invden[0];
#pragma unroll
    for (int m = 1; m <= 60; ++m)
        dp[m] = (src[(m + 1) * sstride] - dp[m - 1] * SIXTH) * FAC.invden[m];
    float d63 = src[63 * sstride];
    dp[61] = (src[62 * sstride] - d63 * SIXTH - dp[60] * SIXTH) * FAC.invden[61];

    float z = dp[61];
    dst[65 * dstride] = 2.0f * d63 - z;
    dst[64 * dstride] = d63;
    dst[63 * dstride] = z;
#pragma unroll
    for (int m = 60; m >= 0; --m) {
        z = dp[m] - FAC.cp[m] * z;
        dst[(m + 2) * dstride] = z;
    }
    dst[dstride] = d0;
    dst[0] = 2.0f * d0 - z;
}

// Fused: stage1 (solve along x, 256 threads) -> smem -> stage2 (along y, 264).
__global__ void coef_fused(const float* __restrict__ data)
{
    extern __shared__ float cx[];      // [4][66][65] = 68,640 B
    int t = threadIdx.x;

    if (t < NCH * M_GRID) {            // 256 threads
        int c  = t >> 6;
        int my = t & 63;
        spline_solve_1d(data + c * (M_GRID * M_GRID) + my, M_GRID,
                        cx + c * (NP2 * CX_PAD) + my, CX_PAD);
    }
    __syncthreads();

    if (t < NCH * NP2) {               // 264 threads
        int c  = t / NP2;
        int jx = t % NP2;
        spline_solve_1d(cx + (c * NP2 + jx) * CX_PAD, 1,
                        g_coefs + jx * (NP2 * NCH) + c, NCH);
    }
}

// ---- interpolation ---------------------------------------------------------

__global__ void __launch_bounds__(256) interp4(
    const float* __restrict__ u, float4* __restrict__ out, int n)
{
    extern __shared__ float4 s[];      // 66*66 float4 = 69,696 B
    const float4* gt = reinterpret_cast<const float4*>(g_coefs);
    for (int i = threadIdx.x; i < NP2 * NP2; i += 256)
        s[i] = gt[i];
    __syncthreads();

    const int lane = threadIdx.x & 31;
    const int dx   = lane & 3;         // x-row owned by this lane
    const int g    = lane >> 2;        // point group 0..7 within warp
    const int gw   = (blockIdx.x * 256 + threadIdx.x) >> 5;
    const int nw   = gridDim.x * 8;

    for (int base = gw * 8; base < n; base += nw * 8) {
        // cooperatively load 8 points' (ux,uy): 16 floats, lanes 0..15
        float uval = 0.0f;
        if (lane < 16) {
            int idx = base * 2 + lane;
            idx = idx < 2 * n - 1 ? idx : 2 * n - 1;
            uval = u[idx];
        }
        float uxr = __shfl_sync(0xffffffffu, uval, 2 * g);
        float uyr = __shfl_sync(0xffffffffu, uval, 2 * g + 1);

        // axis index + fraction (with extrapolation handling)
        float uxn = uxr * 63.0f;
        float fx  = floorf(uxn);
        int   ix  = (int)fx;
        float tx  = uxn - fx;
        if (uxn < 0.0f)   { ix = 0;  tx = uxn; }
        if (uxn >= 62.0f) { ix = 62; tx = uxn - 62.0f; }

        float uyn = uyr * 63.0f;
        float fy  = floorf(uyn);
        int   iy  = (int)fy;
        float ty  = uyn - fy;
        if (uyn < 0.0f)   { iy = 0;  ty = uyn; }
        if (uyn >= 62.0f) { iy = 62; ty = uyn - 62.0f; }

        // cubic B-spline weights (Horner, immediate-form FFMA)
        const float S = 1.0f / 6.0f;
        float wx0 = ((-S * tx + 0.5f) * tx - 0.5f) * tx + S;
        float wx1 = ((0.5f * tx - 1.0f) * tx) * tx + (2.0f / 3.0f);
        float wx2 = ((-0.5f * tx + 0.5f) * tx + 0.5f) * tx + S;
        float wx3 = (S * tx) * tx * tx;
        float wxa = dx == 0 ? wx0 : (dx == 1 ? wx1 : (dx == 2 ? wx2 : wx3));

        float wy0 = ((-S * ty + 0.5f) * ty - 0.5f) * ty + S;
        float wy1 = ((0.5f * ty - 1.0f) * ty) * ty + (2.0f / 3.0f);
        float wy2 = ((-0.5f * ty + 0.5f) * ty + 0.5f) * ty + S;
        float wy3 = (S * ty) * ty * ty;

        float w0 = wxa * wy0, w1 = wxa * wy1, w2 = wxa * wy2, w3 = wxa * wy3;

        // 4 conflict-engineered LDS.128: this lane's x-row, y..y+3
        const float4* rowp = s + (ix + dx) * NP2 + iy;
        float4 v0 = rowp[0], v1 = rowp[1], v2 = rowp[2], v3 = rowp[3];

        float ax = v0.x * w0 + v1.x * w1 + v2.x * w2 + v3.x * w3;
        float ay = v0.y * w0 + v1.y * w1 + v2.y * w2 + v3.y * w3;
        float az = v0.z * w0 + v1.z * w1 + v2.z * w2 + v3.z * w3;
        float aw = v0.w * w0 + v1.w * w1 + v2.w * w2 + v3.w * w3;

        // butterfly reduce over the 4 dx lanes
        ax += __shfl_xor_sync(0xffffffffu, ax, 1);
        ay += __shfl_xor_sync(0xffffffffu, ay, 1);
        az += __shfl_xor_sync(0xffffffffu, az, 1);
        aw += __shfl_xor_sync(0xffffffffu, aw, 1);
        ax += __shfl_xor_sync(0xffffffffu, ax, 2);
        ay += __shfl_xor_sync(0xffffffffu, ay, 2);
        az += __shfl_xor_sync(0xffffffffu, az, 2);
        aw += __shfl_xor_sync(0xffffffffu, aw, 2);

        int p = base + g;
        if (dx == 0 && p < n)
            out[p] = make_float4(ax, ay, az, aw);
    }
}

extern "C" void kernel_launch(void* const* d_in, const int* in_sizes, int n_in,
                              void* d_out, int out_size)
{
    const float* u    = (const float*)d_in[0];
    const float* data = (const float*)d_in[1];
    int n = in_sizes[0] / 2;

    const int coef_smem   = NCH * NP2 * CX_PAD * (int)sizeof(float);   // 68,640
    const int interp_smem = NP2 * NP2 * (int)sizeof(float4);           // 69,696
    cudaFuncSetAttribute(coef_fused,
                         cudaFuncAttributeMaxDynamicSharedMemorySize, coef_smem);
    cudaFuncSetAttribute(interp4,
                         cudaFuncAttributeMaxDynamicSharedMemorySize, interp_smem);

    coef_fused<<<1, 288, coef_smem>>>(data);
    interp4<<<444, 256, interp_smem>>>(u, (float4*)d_out, n);
}

// round 3
// speedup vs baseline: 1.3626x; 1.3626x over previous
#include <cuda_runtime.h>
#include <cuda_fp16.h>

// ---------------------------------------------------------------------------
// InterpolatingBSpline2d, round 3.
//
// Coef solve: fused two-pass Thomas with compile-time factors (as round 2),
// now emitting an fp16 DUAL SHIFTED-COPY table:
//   copy0[(x*66+y)*4+c]  = coef(x, y,   c)
//   copy1[(x*66+y)*4+c]  = coef(x, y+1, c)
// For a query with y-cell iy: pick copy (iy&1), base y = iy&~1. The 16 halfs
// (4 y-taps x 4 channels) for each x-row are then TWO aligned 16B chunks ->
// 8x LDS.128 per point, 128 B/point (half of round 1/2's 256 B).
//
// Interp: per-thread gather (no shfl), fp32 accumulation.
// ---------------------------------------------------------------------------

#define M_GRID   64
#define NP2      66
#define NINNER   62
#define NCH      4
#define CX_PAD   65
#define COPY_HALFS (NP2 * NP2 * NCH)      // 17424 halfs = 34,848 B per copy

__device__ __half g_tab[2 * COPY_HALFS];  // 69,696 B

// ---- compile-time Thomas factors ------------------------------------------
struct Fac { float cp[NINNER]; float invden[NINNER]; };

constexpr Fac make_fac() {
    Fac f{};
    const float B = 2.0f / 3.0f, A = 1.0f / 6.0f;
    float c = A / B;
    f.cp[0] = c;
    f.invden[0] = 1.0f / B;
    for (int m = 1; m < NINNER; ++m) {
        float den = B - A * c;
        float inv = 1.0f / den;
        c = A * inv;
        f.cp[m] = c;
        f.invden[m] = inv;
    }
    return f;
}
__constant__ Fac FAC = make_fac();

// Solve 66-unknown natural-BC spline system for one 64-sample RHS.
template <typename T>
__device__ __forceinline__ void spline_solve_1d(
    const float* __restrict__ src, int sstride,
    T* __restrict__ dst, int dstride)
{
    const float SIXTH = 1.0f / 6.0f;
    float d0 = src[0];
    float dp[NINNER];

    dp[0] = (src[sstride] - d0 * SIXTH) * FAC.invden[0];
#pragma unroll
    for (int m = 1; m <= 60; ++m)
        dp[m] = (src[(m + 1) * sstride] - dp[m - 1] * SIXTH) * FAC.invden[m];
    float d63 = src[63 * sstride];
    dp[61] = (src[62 * sstride] - d63 * SIXTH - dp[60] * SIXTH) * FAC.invden[61];

    float z = dp[61];
    dst[65 * dstride] = (T)(2.0f * d63 - z);
    dst[64 * dstride] = (T)d63;
    dst[63 * dstride] = (T)z;
#pragma unroll
    for (int m = 60; m >= 0; --m) {
        z = dp[m] - FAC.cp[m] * z;
        dst[(m + 2) * dstride] = (T)z;
    }
    dst[dstride] = (T)d0;
    dst[0] = (T)(2.0f * d0 - z);
}

// Fused coef kernel: stage1 (x-solve, fp32 smem) -> stage2 (y-solve, half
// copy0 in global) -> shifted copy1.
__global__ void coef_fused(const float* __restrict__ data)
{
    extern __shared__ float cx[];      // [4][66][65] = 68,640 B
    int t = threadIdx.x;

    if (t < NCH * M_GRID) {            // 256 threads: solve along x
        int c  = t >> 6;
        int my = t & 63;
        spline_solve_1d(data + c * (M_GRID * M_GRID) + my, M_GRID,
                        cx + c * (NP2 * CX_PAD) + my, CX_PAD);
    }
    __syncthreads();

    if (t < NCH * NP2) {               // 264 threads: solve along y -> copy0
        int c  = t / NP2;
        int jx = t % NP2;
        spline_solve_1d(cx + (c * NP2 + jx) * CX_PAD, 1,
                        g_tab + jx * (NP2 * NCH) + c, NCH);
    }
    __syncthreads();                   // copy0 visible block-wide

    // copy1[i] = copy0[i + 4 halfs]  (shift by one y-slot); 8B granules.
    // Entries landing in unused y=65 slots may hold garbage - never read.
    unsigned long long* t64 = reinterpret_cast<unsigned long long*>(g_tab);
    const int n64 = COPY_HALFS / 4;    // 4356
    for (int i = t; i < n64 - 1; i += blockDim.x)
        t64[n64 + i] = t64[i + 1];
}

// ---- interpolation ---------------------------------------------------------

__device__ __forceinline__ float2 h2f(unsigned v)
{
    __half2 h = *reinterpret_cast<const __half2*>(&v);
    return __half22float2(h);
}

__global__ void __launch_bounds__(256) interp_h(
    const float2* __restrict__ u, float4* __restrict__ out, int n)
{
    extern __shared__ __align__(16) __half s[];   // 69,696 B (both copies)
    {
        const uint4* gt = reinterpret_cast<const uint4*>(g_tab);
        uint4* st = reinterpret_cast<uint4*>(s);
        for (int i = threadIdx.x; i < 2 * COPY_HALFS / 8; i += 256)
            st[i] = gt[i];
    }
    __syncthreads();

    const float S = 1.0f / 6.0f;
    int stride = gridDim.x * blockDim.x;
    for (int i = blockIdx.x * blockDim.x + threadIdx.x; i < n; i += stride) {
        float2 p = u[i];
        float uxn = p.x * 63.0f;
        float fx  = floorf(uxn);
        int   ix  = (int)fx;
        float tx  = uxn - fx;
        if (uxn < 0.0f)   { ix = 0;  tx = uxn; }
        if (uxn >= 62.0f) { ix = 62; tx = uxn - 62.0f; }

        float uyn = p.y * 63.0f;
        float fy  = floorf(uyn);
        int   iy  = (int)fy;
        float ty  = uyn - fy;
        if (uyn < 0.0f)   { iy = 0;  ty = uyn; }
        if (uyn >= 62.0f) { iy = 62; ty = uyn - 62.0f; }

        // cubic B-spline weights (Horner)
        float wx0 = ((-S * tx + 0.5f) * tx - 0.5f) * tx + S;
        float wx1 = ((0.5f * tx - 1.0f) * tx) * tx + (2.0f / 3.0f);
        float wx2 = ((-0.5f * tx + 0.5f) * tx + 0.5f) * tx + S;
        float wx3 = (S * tx) * tx * tx;

        float wy0 = ((-S * ty + 0.5f) * ty - 0.5f) * ty + S;
        float wy1 = ((0.5f * ty - 1.0f) * ty) * ty + (2.0f / 3.0f);
        float wy2 = ((-0.5f * ty + 0.5f) * ty + 0.5f) * ty + S;
        float wy3 = (S * ty) * ty * ty;

        // Dual-copy select: copy (iy&1), base y = iy&~1. Each x-row's 16
        // halfs are two aligned 16B chunks in y-major (c0..c3 per y) order.
        int iy2 = iy & ~1;
        const uint4* bp = reinterpret_cast<const uint4*>(
            s + (iy & 1) * COPY_HALFS + (ix * NP2 + iy2) * NCH);

        float acc0 = 0.0f, acc1 = 0.0f, acc2 = 0.0f, acc3 = 0.0f;
#pragma unroll
        for (int dx = 0; dx < 4; ++dx) {
            uint4 qa = bp[dx * 33];        // y-taps 0,1 (each: c01, c23)
            uint4 qb = bp[dx * 33 + 1];    // y-taps 2,3
            float2 a01 = h2f(qa.x), a23 = h2f(qa.y);
            float2 b01 = h2f(qa.z), b23 = h2f(qa.w);
            float2 c01 = h2f(qb.x), c23 = h2f(qb.y);
            float2 d01 = h2f(qb.z), d23 = h2f(qb.w);

            float r0 = a01.x * wy0 + b01.x * wy1 + c01.x * wy2 + d01.x * wy3;
            float r1 = a01.y * wy0 + b01.y * wy1 + c01.y * wy2 + d01.y * wy3;
            float r2 = a23.x * wy0 + b23.x * wy1 + c23.x * wy2 + d23.x * wy3;
            float r3 = a23.y * wy0 + b23.y * wy1 + c23.y * wy2 + d23.y * wy3;

            float wx = (dx == 0) ? wx0 : (dx == 1) ? wx1 : (dx == 2) ? wx2 : wx3;
            acc0 += wx * r0;
            acc1 += wx * r1;
            acc2 += wx * r2;
            acc3 += wx * r3;
        }
        out[i] = make_float4(acc0, acc1, acc2, acc3);
    }
}

extern "C" void kernel_launch(void* const* d_in, const int* in_sizes, int n_in,
                              void* d_out, int out_size)
{
    const float2* u    = (const float2*)d_in[0];
    const float*  data = (const float*)d_in[1];
    int n = in_sizes[0] / 2;

    const int coef_smem   = NCH * NP2 * CX_PAD * (int)sizeof(float);   // 68,640
    const int interp_smem = 2 * COPY_HALFS * (int)sizeof(__half);      // 69,696
    cudaFuncSetAttribute(coef_fused,
                         cudaFuncAttributeMaxDynamicSharedMemorySize, coef_smem);
    cudaFuncSetAttribute(interp_h,
                         cudaFuncAttributeMaxDynamicSharedMemorySize, interp_smem);

    coef_fused<<<1, 288, coef_smem>>>(data);
    interp_h<<<444, 256, interp_smem>>>(u, (float4*)d_out, n);
}

// round 4
// speedup vs baseline: 1.6274x; 1.1944x over previous
#include <cuda_runtime.h>
#include <cuda_fp16.h>

// ---------------------------------------------------------------------------
// InterpolatingBSpline2d, round 4.
//
// Coef solve (1 block): fused two-pass Thomas, compile-time factors, emits
// ONLY copy0 of the fp16 table to global. (Round 3 also built the shifted
// copy1 in global here; that work moves to the interp kernel's smem fill.)
//
// Interp: fp16 dual shifted-copy table in smem (copy1 built during the fill
// from copy0, shifted one y-slot = one 8-byte granule). 8x LDS.128 / point.
// KEY CHANGE vs round 3: 512-thread blocks. Smem (69.7 KB) caps us at
// 3 blocks/SM either way, so 512 threads/block doubles resident warps
// (768 -> 1536 threads/SM) and the latency hiding that was the R3 bind.
// ---------------------------------------------------------------------------

#define M_GRID   64
#define NP2      66
#define NINNER   62
#define NCH      4
#define CX_PAD   65
#define COPY_HALFS (NP2 * NP2 * NCH)      // 17424 halfs = 34,848 B per copy

__device__ __half g_tab[COPY_HALFS];      // copy0 only

// ---- compile-time Thomas factors ------------------------------------------
struct Fac { float cp[NINNER]; float invden[NINNER]; };

constexpr Fac make_fac() {
    Fac f{};
    const float B = 2.0f / 3.0f, A = 1.0f / 6.0f;
    float c = A / B;
    f.cp[0] = c;
    f.invden[0] = 1.0f / B;
    for (int m = 1; m < NINNER; ++m) {
        float den = B - A * c;
        float inv = 1.0f / den;
        c = A * inv;
        f.cp[m] = c;
        f.invden[m] = inv;
    }
    return f;
}
__constant__ Fac FAC = make_fac();

// Solve 66-unknown natural-BC spline system for one 64-sample RHS.
template <typename T>
__device__ __forceinline__ void spline_solve_1d(
    const float* __restrict__ src, int sstride,
    T* __restrict__ dst, int dstride)
{
    const float SIXTH = 1.0f / 6.0f;
    float d0 = src[0];
    float dp[NINNER];

    dp[0] = (src[sstride] - d0 * SIXTH) * FAC.invden[0];
#pragma unroll
    for (int m = 1; m <= 60; ++m)
        dp[m] = (src[(m + 1) * sstride] - dp[m - 1] * SIXTH) * FAC.invden[m];
    float d63 = src[63 * sstride];
    dp[61] = (src[62 * sstride] - d63 * SIXTH - dp[60] * SIXTH) * FAC.invden[61];

    float z = dp[61];
    dst[65 * dstride] = (T)(2.0f * d63 - z);
    dst[64 * dstride] = (T)d63;
    dst[63 * dstride] = (T)z;
#pragma unroll
    for (int m = 60; m >= 0; --m) {
        z = dp[m] - FAC.cp[m] * z;
        dst[(m + 2) * dstride] = (T)z;
    }
    dst[dstride] = (T)d0;
    dst[0] = (T)(2.0f * d0 - z);
}

// Fused coef kernel: stage1 (x-solve, fp32 smem) -> stage2 (y-solve -> copy0).
__global__ void coef_fused(const float* __restrict__ data)
{
    extern __shared__ float cx[];      // [4][66][65] = 68,640 B
    int t = threadIdx.x;

    if (t < NCH * M_GRID) {            // 256 threads: solve along x
        int c  = t >> 6;
        int my = t & 63;
        spline_solve_1d(data + c * (M_GRID * M_GRID) + my, M_GRID,
                        cx + c * (NP2 * CX_PAD) + my, CX_PAD);
    }
    __syncthreads();

    if (t < NCH * NP2) {               // 264 threads: solve along y -> copy0
        int c  = t / NP2;
        int jx = t % NP2;
        spline_solve_1d(cx + (c * NP2 + jx) * CX_PAD, 1,
                        g_tab + jx * (NP2 * NCH) + c, NCH);
    }
}

// ---- interpolation ---------------------------------------------------------

__device__ __forceinline__ float2 h2f(unsigned v)
{
    __half2 h = *reinterpret_cast<const __half2*>(&v);
    return __half22float2(h);
}

__global__ void __launch_bounds__(512) interp_h(
    const float2* __restrict__ u, float4* __restrict__ out, int n)
{
    extern __shared__ __align__(16) __half s[];   // 69,696 B (both copies)
    {
        // copy0: wide 16B loads
        const uint4* g16 = reinterpret_cast<const uint4*>(g_tab);
        uint4* s16 = reinterpret_cast<uint4*>(s);
        const int n16 = COPY_HALFS / 8;           // 2178
        for (int i = threadIdx.x; i < n16; i += blockDim.x)
            s16[i] = g16[i];
        // copy1 = copy0 shifted by one y-slot (8 bytes)
        const unsigned long long* g64 =
            reinterpret_cast<const unsigned long long*>(g_tab);
        unsigned long long* s64 = reinterpret_cast<unsigned long long*>(s);
        const int n64 = COPY_HALFS / 4;           // 4356
        for (int i = threadIdx.x; i < n64 - 1; i += blockDim.x)
            s64[n64 + i] = g64[i + 1];
    }
    __syncthreads();

    const float S = 1.0f / 6.0f;
    int stride = gridDim.x * blockDim.x;
    for (int i = blockIdx.x * blockDim.x + threadIdx.x; i < n; i += stride) {
        float2 p = u[i];
        float uxn = p.x * 63.0f;
        float fx  = floorf(uxn);
        int   ix  = (int)fx;
        float tx  = uxn - fx;
        if (uxn < 0.0f)   { ix = 0;  tx = uxn; }
        if (uxn >= 62.0f) { ix = 62; tx = uxn - 62.0f; }

        float uyn = p.y * 63.0f;
        float fy  = floorf(uyn);
        int   iy  = (int)fy;
        float ty  = uyn - fy;
        if (uyn < 0.0f)   { iy = 0;  ty = uyn; }
        if (uyn >= 62.0f) { iy = 62; ty = uyn - 62.0f; }

        // cubic B-spline weights (Horner)
        float wx0 = ((-S * tx + 0.5f) * tx - 0.5f) * tx + S;
        float wx1 = ((0.5f * tx - 1.0f) * tx) * tx + (2.0f / 3.0f);
        float wx2 = ((-0.5f * tx + 0.5f) * tx + 0.5f) * tx + S;
        float wx3 = (S * tx) * tx * tx;

        float wy0 = ((-S * ty + 0.5f) * ty - 0.5f) * ty + S;
        float wy1 = ((0.5f * ty - 1.0f) * ty) * ty + (2.0f / 3.0f);
        float wy2 = ((-0.5f * ty + 0.5f) * ty + 0.5f) * ty + S;
        float wy3 = (S * ty) * ty * ty;

        // Dual-copy select: copy (iy&1), base y = iy&~1. Each x-row's 16
        // halfs are two aligned 16B chunks (y-major, c fastest).
        int iy2 = iy & ~1;
        const uint4* bp = reinterpret_cast<const uint4*>(
            s + (iy & 1) * COPY_HALFS + (ix * NP2 + iy2) * NCH);

        float acc0 = 0.0f, acc1 = 0.0f, acc2 = 0.0f, acc3 = 0.0f;
#pragma unroll
        for (int dx = 0; dx < 4; ++dx) {
            uint4 qa = bp[dx * 33];        // y-taps 0,1 (each: c01, c23)
            uint4 qb = bp[dx * 33 + 1];    // y-taps 2,3
            float2 a01 = h2f(qa.x), a23 = h2f(qa.y);
            float2 b01 = h2f(qa.z), b23 = h2f(qa.w);
            float2 c01 = h2f(qb.x), c23 = h2f(qb.y);
            float2 d01 = h2f(qb.z), d23 = h2f(qb.w);

            float r0 = a01.x * wy0 + b01.x * wy1 + c01.x * wy2 + d01.x * wy3;
            float r1 = a01.y * wy0 + b01.y * wy1 + c01.y * wy2 + d01.y * wy3;
            float r2 = a23.x * wy0 + b23.x * wy1 + c23.x * wy2 + d23.x * wy3;
            float r3 = a23.y * wy0 + b23.y * wy1 + c23.y * wy2 + d23.y * wy3;

            float wx = (dx == 0) ? wx0 : (dx == 1) ? wx1 : (dx == 2) ? wx2 : wx3;
            acc0 += wx * r0;
            acc1 += wx * r1;
            acc2 += wx * r2;
            acc3 += wx * r3;
        }
        out[i] = make_float4(acc0, acc1, acc2, acc3);
    }
}

extern "C" void kernel_launch(void* const* d_in, const int* in_sizes, int n_in,
                              void* d_out, int out_size)
{
    const float2* u    = (const float2*)d_in[0];
    const float*  data = (const float*)d_in[1];
    int n = in_sizes[0] / 2;

    const int coef_smem   = NCH * NP2 * CX_PAD * (int)sizeof(float);   // 68,640
    const int interp_smem = 2 * COPY_HALFS * (int)sizeof(__half);      // 69,696
    cudaFuncSetAttribute(coef_fused,
                         cudaFuncAttributeMaxDynamicSharedMemorySize, coef_smem);
    cudaFuncSetAttribute(interp_h,
                         cudaFuncAttributeMaxDynamicSharedMemorySize, interp_smem);

    coef_fused<<<1, 288, coef_smem>>>(data);
    interp_h<<<444, 512, interp_smem>>>(u, (float4*)d_out, n);
}

// round 5
// speedup vs baseline: 1.9548x; 1.2011x over previous
#include <cuda_runtime.h>
#include <cuda_fp16.h>

// ---------------------------------------------------------------------------
// InterpolatingBSpline2d, round 5.
//
// Coef solve (1 block): fused two-pass Thomas, compile-time factors, fp32
// output table (x*66+y)*4+c. ROUND-4 LESSON: emitting __half (scattered
// STG.U16) from this kernel cost ~15us vs the identical fp32-emitting
// kernel (R2 gap 5.5us vs R4 gap 20.8us) -> keep coef output fp32.
//
// Interp: fp16 dual shifted-copy table in smem. The float->half conversion
// AND the shifted copy1 are built during the smem fill (one LDG.128 per
// table slot, two 8B STS). Gather loop: 8x LDS.128 / point, fp32 math.
// 512-thread blocks, 3 blocks/SM (smem-capped), 444 = 148x3 single wave.
// ---------------------------------------------------------------------------

#define M_GRID   64
#define NP2      66
#define NINNER   62
#define NCH      4
#define CX_PAD   65
#define NSLOT    (NP2 * NP2)              // 4356 (x,y) slots
#define COPY_HALFS (NSLOT * NCH)          // 17424 halfs = 34,848 B per copy

__device__ float g_coefs[NSLOT * NCH];    // fp32 table, (x*66+y)*4+c

// ---- compile-time Thomas factors ------------------------------------------
struct Fac { float cp[NINNER]; float invden[NINNER]; };

constexpr Fac make_fac() {
    Fac f{};
    const float B = 2.0f / 3.0f, A = 1.0f / 6.0f;
    float c = A / B;
    f.cp[0] = c;
    f.invden[0] = 1.0f / B;
    for (int m = 1; m < NINNER; ++m) {
        float den = B - A * c;
        float inv = 1.0f / den;
        c = A * inv;
        f.cp[m] = c;
        f.invden[m] = inv;
    }
    return f;
}
__constant__ Fac FAC = make_fac();

// Solve 66-unknown natural-BC spline system for one 64-sample RHS.
__device__ __forceinline__ void spline_solve_1d(
    const float* __restrict__ src, int sstride,
    float* __restrict__ dst, int dstride)
{
    const float SIXTH = 1.0f / 6.0f;
    float d0 = src[0];
    float dp[NINNER];

    dp[0] = (src[sstride] - d0 * SIXTH) * FAC.invden[0];
#pragma unroll
    for (int m = 1; m <= 60; ++m)
        dp[m] = (src[(m + 1) * sstride] - dp[m - 1] * SIXTH) * FAC.invden[m];
    float d63 = src[63 * sstride];
    dp[61] = (src[62 * sstride] - d63 * SIXTH - dp[60] * SIXTH) * FAC.invden[61];

    float z = dp[61];
    dst[65 * dstride] = 2.0f * d63 - z;
    dst[64 * dstride] = d63;
    dst[63 * dstride] = z;
#pragma unroll
    for (int m = 60; m >= 0; --m) {
        z = dp[m] - FAC.cp[m] * z;
        dst[(m + 2) * dstride] = z;
    }
    dst[dstride] = d0;
    dst[0] = 2.0f * d0 - z;
}

// Fused coef kernel: stage1 (x-solve, fp32 smem) -> stage2 (y-solve -> fp32).
__global__ void coef_fused(const float* __restrict__ data)
{
    extern __shared__ float cx[];      // [4][66][65] = 68,640 B
    int t = threadIdx.x;

    if (t < NCH * M_GRID) {            // 256 threads: solve along x
        int c  = t >> 6;
        int my = t & 63;
        spline_solve_1d(data + c * (M_GRID * M_GRID) + my, M_GRID,
                        cx + c * (NP2 * CX_PAD) + my, CX_PAD);
    }
    __syncthreads();

    if (t < NCH * NP2) {               // 264 threads: solve along y
        int c  = t / NP2;
        int jx = t % NP2;
        spline_solve_1d(cx + (c * NP2 + jx) * CX_PAD, 1,
                        g_coefs + jx * (NP2 * NCH) + c, NCH);
    }
}

// ---- interpolation ---------------------------------------------------------

__device__ __forceinline__ float2 h2f(unsigned v)
{
    __half2 h = *reinterpret_cast<const __half2*>(&v);
    return __half22float2(h);
}

__global__ void __launch_bounds__(512) interp_h(
    const float2* __restrict__ u, float4* __restrict__ out, int n)
{
    extern __shared__ __align__(16) __half s[];   // 69,696 B (both copies)
    {
        // One float4 read per slot -> half4 -> copy0[j] and copy1[j-1].
        const float4* gf = reinterpret_cast<const float4*>(g_coefs);
        uint2* s64 = reinterpret_cast<uint2*>(s);
        for (int j = threadIdx.x; j < NSLOT; j += blockDim.x) {
            float4 v = gf[j];
            __half2 h01 = __float22half2_rn(make_float2(v.x, v.y));
            __half2 h23 = __float22half2_rn(make_float2(v.z, v.w));
            uint2 pk;
            pk.x = *reinterpret_cast<unsigned*>(&h01);
            pk.y = *reinterpret_cast<unsigned*>(&h23);
            s64[j] = pk;                               // copy0, slot j
            if (j > 0)
                s64[NSLOT + j - 1] = pk;               // copy1, slot j-1
        }
    }
    __syncthreads();

    const float S = 1.0f / 6.0f;
    int stride = gridDim.x * blockDim.x;
    for (int i = blockIdx.x * blockDim.x + threadIdx.x; i < n; i += stride) {
        float2 p = u[i];
        float uxn = p.x * 63.0f;
        float fx  = floorf(uxn);
        int   ix  = (int)fx;
        float tx  = uxn - fx;
        if (uxn < 0.0f)   { ix = 0;  tx = uxn; }
        if (uxn >= 62.0f) { ix = 62; tx = uxn - 62.0f; }

        float uyn = p.y * 63.0f;
        float fy  = floorf(uyn);
        int   iy  = (int)fy;
        float ty  = uyn - fy;
        if (uyn < 0.0f)   { iy = 0;  ty = uyn; }
        if (uyn >= 62.0f) { iy = 62; ty = uyn - 62.0f; }

        // cubic B-spline weights (Horner)
        float wx0 = ((-S * tx + 0.5f) * tx - 0.5f) * tx + S;
        float wx1 = ((0.5f * tx - 1.0f) * tx) * tx + (2.0f / 3.0f);
        float wx2 = ((-0.5f * tx + 0.5f) * tx + 0.5f) * tx + S;
        float wx3 = (S * tx) * tx * tx;

        float wy0 = ((-S * ty + 0.5f) * ty - 0.5f) * ty + S;
        float wy1 = ((0.5f * ty - 1.0f) * ty) * ty + (2.0f / 3.0f);
        float wy2 = ((-0.5f * ty + 0.5f) * ty + 0.5f) * ty + S;
        float wy3 = (S * ty) * ty * ty;

        // Dual-copy select: copy (iy&1), base y = iy&~1. Each x-row's 16
        // halfs are two aligned 16B chunks (y-major, c fastest).
        int iy2 = iy & ~1;
        const uint4* bp = reinterpret_cast<const uint4*>(
            s + (iy & 1) * COPY_HALFS + (ix * NP2 + iy2) * NCH);

        float acc0 = 0.0f, acc1 = 0.0f, acc2 = 0.0f, acc3 = 0.0f;
#pragma unroll
        for (int dx = 0; dx < 4; ++dx) {
            uint4 qa = bp[dx * 33];        // y-taps 0,1 (each: c01, c23)
            uint4 qb = bp[dx * 33 + 1];    // y-taps 2,3
            float2 a01 = h2f(qa.x), a23 = h2f(qa.y);
            float2 b01 = h2f(qa.z), b23 = h2f(qa.w);
            float2 c01 = h2f(qb.x), c23 = h2f(qb.y);
            float2 d01 = h2f(qb.z), d23 = h2f(qb.w);

            float r0 = a01.x * wy0 + b01.x * wy1 + c01.x * wy2 + d01.x * wy3;
            float r1 = a01.y * wy0 + b01.y * wy1 + c01.y * wy2 + d01.y * wy3;
            float r2 = a23.x * wy0 + b23.x * wy1 + c23.x * wy2 + d23.x * wy3;
            float r3 = a23.y * wy0 + b23.y * wy1 + c23.y * wy2 + d23.y * wy3;

            float wx = (dx == 0) ? wx0 : (dx == 1) ? wx1 : (dx == 2) ? wx2 : wx3;
            acc0 += wx * r0;
            acc1 += wx * r1;
            acc2 += wx * r2;
            acc3 += wx * r3;
        }
        out[i] = make_float4(acc0, acc1, acc2, acc3);
    }
}

extern "C" void kernel_launch(void* const* d_in, const int* in_sizes, int n_in,
                              void* d_out, int out_size)
{
    const float2* u    = (const float2*)d_in[0];
    const float*  data = (const float*)d_in[1];
    int n = in_sizes[0] / 2;

    const int coef_smem   = NCH * NP2 * CX_PAD * (int)sizeof(float);   // 68,640
    const int interp_smem = 2 * COPY_HALFS * (int)sizeof(__half);      // 69,696
    cudaFuncSetAttribute(coef_fused,
                         cudaFuncAttributeMaxDynamicSharedMemorySize, coef_smem);
    cudaFuncSetAttribute(interp_h,
                         cudaFuncAttributeMaxDynamicSharedMemorySize, interp_smem);

    coef_fused<<<1, 288, coef_smem>>>(data);
    interp_h<<<444, 512, interp_smem>>>(u, (float4*)d_out, n);
}